// round 1
// baseline (speedup 1.0000x reference)
#include <cuda_runtime.h>
#include <math.h>

// Problem dims (fixed for this problem instance)
#define N_TOK 32768
#define L_SEQ 512
#define B_ROWS 64
#define HDIM 768
#define EDIM 1000
#define PDIM 300
#define QLD  1024   // padded leading dim for Q

// ---------------- scratch (__device__ globals; no allocations allowed) ----------------
__device__ float g_means[(size_t)N_TOK * HDIM];  // segment means (reused across both label sets)
__device__ float g_P[EDIM * PDIM];               // proj_desc = ent @ w_desc   [E,P]
__device__ float g_Pt[PDIM * EDIM];              // transpose [P,E]
__device__ float g_Q[HDIM * QLD];                // Q = w_mention @ proj_desc^T  [H,E] ld=QLD
__device__ int   g_pred[N_TOK];                  // predicted labels
__device__ int   g_nzTok[N_TOK];                 // stream pos -> token index
__device__ int   g_cumB[N_TOK];                  // inclusive B-count by stream pos
__device__ int   g_segStart[N_TOK];              // start stream-pos per segment
__device__ int   g_outRow[N_TOK];                // segment -> output row (b*L + j)
__device__ int   g_c[2][B_ROWS];                 // per-row B counts, per set
__device__ int   g_hdr[3];                       // M (nonzero count), C (segment count), idx0

// ============================= fused MLP kernel =============================
// logits = relu(hidden @ w1 + b1) @ w2 + b2 ; write log_softmax + argmax
__global__ __launch_bounds__(256) void mlp_kernel(
    const float* __restrict__ hidden, const float* __restrict__ w1,
    const float* __restrict__ b1, const float* __restrict__ w2,
    const float* __restrict__ b2, float* __restrict__ out_logits)
{
    __shared__ float As[8][132];
    __shared__ float Bs[8][128];
    __shared__ float w2s[128][3];
    __shared__ float b1s[128];

    const int tid = threadIdx.x;
    const int tx = tid & 15, ty = tid >> 4;
    const int row0 = blockIdx.x * 128;

    float plog[8][3];
#pragma unroll
    for (int i = 0; i < 8; i++) { plog[i][0] = 0.f; plog[i][1] = 0.f; plog[i][2] = 0.f; }

    for (int jt = 0; jt < HDIM; jt += 128) {
        if (tid < 128) {
            b1s[tid]    = b1[jt + tid];
            w2s[tid][0] = w2[(jt + tid) * 3 + 0];
            w2s[tid][1] = w2[(jt + tid) * 3 + 1];
            w2s[tid][2] = w2[(jt + tid) * 3 + 2];
        }
        float acc[8][8];
#pragma unroll
        for (int i = 0; i < 8; i++)
#pragma unroll
            for (int j = 0; j < 8; j++) acc[i][j] = 0.f;

        for (int k0 = 0; k0 < HDIM; k0 += 8) {
            __syncthreads();
#pragma unroll
            for (int t = 0; t < 4; t++) {
                int e = tid + t * 256;
                int r = e >> 3, kk = e & 7;
                As[kk][r] = hidden[(size_t)(row0 + r) * HDIM + k0 + kk];
            }
#pragma unroll
            for (int t = 0; t < 4; t++) {
                int e = tid + t * 256;
                int kk = e >> 7, c = e & 127;
                Bs[kk][c] = w1[(size_t)(k0 + kk) * HDIM + jt + c];
            }
            __syncthreads();
#pragma unroll
            for (int kk = 0; kk < 8; kk++) {
                float ra[8], rb[8];
#pragma unroll
                for (int i = 0; i < 8; i++) ra[i] = As[kk][i * 16 + ty];
#pragma unroll
                for (int j = 0; j < 8; j++) rb[j] = Bs[kk][j * 16 + tx];
#pragma unroll
                for (int i = 0; i < 8; i++)
#pragma unroll
                    for (int j = 0; j < 8; j++) acc[i][j] += ra[i] * rb[j];
            }
        }
        __syncthreads();
#pragma unroll
        for (int j = 0; j < 8; j++) {
            int col = j * 16 + tx;
            float w20 = w2s[col][0], w21 = w2s[col][1], w22 = w2s[col][2];
            float bb = b1s[col];
#pragma unroll
            for (int i = 0; i < 8; i++) {
                float h = fmaxf(acc[i][j] + bb, 0.f);
                plog[i][0] += h * w20;
                plog[i][1] += h * w21;
                plog[i][2] += h * w22;
            }
        }
        __syncthreads();
    }
    // reduce over tx (16 lanes; rows depend only on ty)
#pragma unroll
    for (int i = 0; i < 8; i++)
#pragma unroll
        for (int k = 0; k < 3; k++) {
            float v = plog[i][k];
            v += __shfl_down_sync(0xffffffffu, v, 8, 16);
            v += __shfl_down_sync(0xffffffffu, v, 4, 16);
            v += __shfl_down_sync(0xffffffffu, v, 2, 16);
            v += __shfl_down_sync(0xffffffffu, v, 1, 16);
            plog[i][k] = v;
        }
    if (tx == 0) {
        float bb0 = b2[0], bb1 = b2[1], bb2 = b2[2];
#pragma unroll
        for (int i = 0; i < 8; i++) {
            int row = row0 + i * 16 + ty;
            float l0 = plog[i][0] + bb0;
            float l1 = plog[i][1] + bb1;
            float l2 = plog[i][2] + bb2;
            float m = fmaxf(l0, fmaxf(l1, l2));
            float lse = m + logf(expf(l0 - m) + expf(l1 - m) + expf(l2 - m));
            out_logits[(size_t)row * 3 + 0] = l0 - lse;
            out_logits[(size_t)row * 3 + 1] = l1 - lse;
            out_logits[(size_t)row * 3 + 2] = l2 - lse;
            int a = 0;
            if (l1 > l0) a = 1;
            float la = (a == 1) ? l1 : l0;
            if (l2 > la) a = 2;
            g_pred[row] = a;
        }
    }
}

// ============================= generic tiled GEMM =============================
// C[M,N] = A[M,K] @ B[K,N], row-major, guards everywhere.
// DYNM: effective M read from g_hdr[1] (=C). REMAP: output row via g_outRow.
template <bool DYNM, bool REMAP>
__global__ __launch_bounds__(256) void gemm_tiled(
    const float* __restrict__ A, const float* __restrict__ Bm, float* __restrict__ Cm,
    int M, int N, int K, int lda, int ldb, int ldc)
{
    __shared__ float As[8][132];
    __shared__ float Bs[8][128];
    const int tid = threadIdx.x;
    const int tx = tid & 15, ty = tid >> 4;
    const int row0 = blockIdx.y * 128, col0 = blockIdx.x * 128;
    const int Meff = DYNM ? g_hdr[1] : M;
    if (row0 >= Meff) return;

    float acc[8][8];
#pragma unroll
    for (int i = 0; i < 8; i++)
#pragma unroll
        for (int j = 0; j < 8; j++) acc[i][j] = 0.f;

    for (int k0 = 0; k0 < K; k0 += 8) {
        __syncthreads();
#pragma unroll
        for (int t = 0; t < 4; t++) {
            int e = tid + t * 256;
            int r = e >> 3, kk = e & 7;
            int gr = row0 + r, gk = k0 + kk;
            As[kk][r] = (gr < Meff && gk < K) ? A[(size_t)gr * lda + gk] : 0.f;
        }
#pragma unroll
        for (int t = 0; t < 4; t++) {
            int e = tid + t * 256;
            int kk = e >> 7, c = e & 127;
            int gk = k0 + kk, gc = col0 + c;
            Bs[kk][c] = (gk < K && gc < N) ? Bm[(size_t)gk * ldb + gc] : 0.f;
        }
        __syncthreads();
#pragma unroll
        for (int kk = 0; kk < 8; kk++) {
            float ra[8], rb[8];
#pragma unroll
            for (int i = 0; i < 8; i++) ra[i] = As[kk][i * 16 + ty];
#pragma unroll
            for (int j = 0; j < 8; j++) rb[j] = Bs[kk][j * 16 + tx];
#pragma unroll
            for (int i = 0; i < 8; i++)
#pragma unroll
                for (int j = 0; j < 8; j++) acc[i][j] += ra[i] * rb[j];
        }
    }
#pragma unroll
    for (int i = 0; i < 8; i++) {
        int r = row0 + i * 16 + ty;
        if (r >= Meff) continue;
        int orow = REMAP ? g_outRow[r] : r;
#pragma unroll
        for (int j = 0; j < 8; j++) {
            int c = col0 + j * 16 + tx;
            if (c < N) Cm[(size_t)orow * ldc + c] = acc[i][j];
        }
    }
}

// ============================= transpose (P -> Pt) =============================
__global__ void transpose_kernel(const float* __restrict__ P, float* __restrict__ Pt,
                                 int rows /*1000*/, int cols /*300*/)
{
    __shared__ float s[32][33];
    int c0 = blockIdx.x * 32, r0 = blockIdx.y * 32;
    int tx = threadIdx.x, ty = threadIdx.y;  // (32,8)
#pragma unroll
    for (int t = 0; t < 4; t++) {
        int r = r0 + ty + t * 8, c = c0 + tx;
        s[ty + t * 8][tx] = (r < rows && c < cols) ? P[(size_t)r * cols + c] : 0.f;
    }
    __syncthreads();
#pragma unroll
    for (int t = 0; t < 4; t++) {
        int r = c0 + ty + t * 8, c = r0 + tx;
        if (r < cols && c < rows) Pt[(size_t)r * rows + c] = s[tx][ty + t * 8];
    }
}

// ============================= scan kernel (1 block) =============================
// Faithfully reproduces the reference's sorted-stream / cumsum / idx0-shift logic.
__global__ void scan_kernel(const int* __restrict__ labels_in, int setIdx, int usePred)
{
    __shared__ int sNZ[1024], sB[1024];
    __shared__ int s_idx0;
    __shared__ int sC[B_ROWS], sSt[B_ROWS];
    const int* lab = usePred ? (const int*)g_pred : labels_in;
    const int tid = threadIdx.x;
    const int IPT = N_TOK / 1024;  // 32
    const int base = tid * IPT;

    int cn = 0, cb = 0;
    for (int t = 0; t < IPT; t++) {
        int l = lab[base + t];
        cn += (l != 0);
        cb += (l == 1);
    }
    sNZ[tid] = cn; sB[tid] = cb;
    if (tid == 0) s_idx0 = N_TOK;
    __syncthreads();
    if (tid == 0) {
        int an = 0, ab = 0;
        for (int t = 0; t < 1024; t++) {
            int n = sNZ[t], b = sB[t];
            sNZ[t] = an; sB[t] = ab;
            an += n; ab += b;
        }
        g_hdr[0] = an;  // M
        g_hdr[1] = ab;  // C
    }
    __syncthreads();
    const int M = g_hdr[0], C = g_hdr[1];
    int pn = sNZ[tid], pb = sB[tid];
    for (int t = 0; t < IPT; t++) {
        int i = base + t;
        int l = lab[i];
        if (l != 0) {
            if (l == 1) { pb++; atomicMin(&s_idx0, pn); }
            g_nzTok[pn] = i;
            g_cumB[pn] = pb;  // inclusive B-count at stream pos pn
            pn++;
        }
    }
    __syncthreads();
    const int idx0 = (C > 0) ? s_idx0 : 0;
    if (tid == 0) g_hdr[2] = idx0;
    // segment starts: seg(p) is nondecreasing, steps <=1, seg(0)=0, seg(M-1)=C-1
    if (C > 0) {
        for (int p = tid; p < M; p += 1024) {
            int q = min(p + idx0, N_TOK - 1);
            int s = ((q < M) ? g_cumB[q] : C) - 1;
            if (p == 0) {
                g_segStart[0] = 0;
            } else {
                int q2 = min(p - 1 + idx0, N_TOK - 1);
                int s2 = ((q2 < M) ? g_cumB[q2] : C) - 1;
                if (s != s2) g_segStart[s] = p;
            }
        }
    }
    // per-row B counts + output row mapping
    if (tid < B_ROWS) {
        int cnt = 0;
        for (int l = 0; l < L_SEQ; l++) cnt += (lab[tid * L_SEQ + l] == 1);
        sC[tid] = cnt;
    }
    __syncthreads();
    if (tid == 0) {
        int a = 0;
        for (int b = 0; b < B_ROWS; b++) { sSt[b] = a; a += sC[b]; }
    }
    __syncthreads();
    if (tid < B_ROWS) {
        g_c[setIdx][tid] = sC[tid];
        int st = sSt[tid];
        for (int j = 0; j < sC[tid]; j++) g_outRow[st + j] = tid * L_SEQ + j;
    }
}

// ============================= segment means =============================
__global__ void means_kernel(const float* __restrict__ hidden)
{
    const int C = g_hdr[1], M = g_hdr[0];
    const int tid = threadIdx.x;  // 256 threads, HDIM = 3*256
    for (int s = blockIdx.x; s < C; s += gridDim.x) {
        int st = g_segStart[s];
        int en = (s + 1 < C) ? g_segStart[s + 1] : M;
        float a0 = 0.f, a1 = 0.f, a2 = 0.f;
        for (int p = st; p < en; p++) {
            const float* h = hidden + (size_t)g_nzTok[p] * HDIM;
            a0 += h[tid];
            a1 += h[tid + 256];
            a2 += h[tid + 512];
        }
        float inv = 1.f / (float)(en - st);
        float* m = g_means + (size_t)s * HDIM;
        m[tid] = a0 * inv;
        m[tid + 256] = a1 * inv;
        m[tid + 512] = a2 * inv;
    }
}

// ============================= row-wise log-softmax over E =============================
__global__ void softmax_kernel(float* __restrict__ scores)  // both sets
{
    __shared__ float red[256];
    const int gid = blockIdx.x;
    const int set = gid >> 15;           // /N_TOK
    const int r = gid & (N_TOK - 1);
    const int b = r / L_SEQ, j = r - b * L_SEQ;
    float* row = scores + (size_t)set * N_TOK * EDIM + (size_t)r * EDIM;
    const int tid = threadIdx.x;
    const int NV = EDIM / 4;  // 250

    if (j >= g_c[set][b]) {
        const float c = -6.9077552789821368f;  // -log(1000): log_softmax of zero logits
        if (tid < NV) reinterpret_cast<float4*>(row)[tid] = make_float4(c, c, c, c);
        return;
    }
    float4 v = make_float4(0.f, 0.f, 0.f, 0.f);
    float m = -3.0e38f;
    if (tid < NV) {
        v = reinterpret_cast<const float4*>(row)[tid];
        m = fmaxf(fmaxf(v.x, v.y), fmaxf(v.z, v.w));
    }
    red[tid] = m;
    __syncthreads();
    for (int s = 128; s > 0; s >>= 1) {
        if (tid < s) red[tid] = fmaxf(red[tid], red[tid + s]);
        __syncthreads();
    }
    float vmax = red[0];
    __syncthreads();
    float se = 0.f;
    if (tid < NV)
        se = expf(v.x - vmax) + expf(v.y - vmax) + expf(v.z - vmax) + expf(v.w - vmax);
    red[tid] = se;
    __syncthreads();
    for (int s = 128; s > 0; s >>= 1) {
        if (tid < s) red[tid] += red[tid + s];
        __syncthreads();
    }
    float lse = vmax + logf(red[0]);
    if (tid < NV) {
        v.x -= lse; v.y -= lse; v.z -= lse; v.w -= lse;
        reinterpret_cast<float4*>(row)[tid] = v;
    }
}

// ============================= launch =============================
extern "C" void kernel_launch(void* const* d_in, const int* in_sizes, int n_in,
                              void* d_out, int out_size)
{
    const int*   labels    = (const int*)d_in[0];
    const float* hidden    = (const float*)d_in[1];
    const float* ent       = (const float*)d_in[2];
    const float* w1        = (const float*)d_in[3];
    const float* b1        = (const float*)d_in[4];
    const float* w2        = (const float*)d_in[5];
    const float* b2        = (const float*)d_in[6];
    const float* w_mention = (const float*)d_in[7];
    const float* w_desc    = (const float*)d_in[8];
    float* out = (float*)d_out;

    void *pP, *pPt, *pQ, *pMeans;
    cudaGetSymbolAddress(&pP, g_P);
    cudaGetSymbolAddress(&pPt, g_Pt);
    cudaGetSymbolAddress(&pQ, g_Q);
    cudaGetSymbolAddress(&pMeans, g_means);

    // 1. fused MLP: bio_slot_logits (out[0:N*3]) + predicted labels
    mlp_kernel<<<N_TOK / 128, 256>>>(hidden, w1, b1, w2, b2, out);

    // 2. Q = w_mention @ (ent @ w_desc)^T
    gemm_tiled<false, false><<<dim3((PDIM + 127) / 128, (EDIM + 127) / 128), 256>>>(
        ent, w_desc, (float*)pP, EDIM, PDIM, HDIM, HDIM, PDIM, PDIM);
    transpose_kernel<<<dim3((PDIM + 31) / 32, (EDIM + 31) / 32), dim3(32, 8)>>>(
        (const float*)pP, (float*)pPt, EDIM, PDIM);
    gemm_tiled<false, false><<<dim3((EDIM + 127) / 128, (HDIM + 127) / 128), 256>>>(
        w_mention, (const float*)pPt, (float*)pQ, HDIM, EDIM, PDIM, PDIM, EDIM, QLD);

    float* score_base = out + (size_t)N_TOK * 3;

    // 3. per label set: scan -> segment means -> dot GEMM (writes into mapped out rows)
    for (int set = 0; set < 2; set++) {
        scan_kernel<<<1, 1024>>>(labels, set, set /*usePred*/);
        means_kernel<<<4096, 256>>>(hidden);
        gemm_tiled<true, true><<<dim3((EDIM + 127) / 128, N_TOK / 128), 256>>>(
            (const float*)pMeans, (const float*)pQ,
            score_base + (size_t)set * N_TOK * EDIM,
            N_TOK, EDIM, HDIM, HDIM, QLD, EDIM);
    }

    // 4. log-softmax over E for all rows (valid in-place; invalid -> -log(E))
    softmax_kernel<<<2 * N_TOK, 256>>>(score_base);
}

// round 2
// speedup vs baseline: 1.0033x; 1.0033x over previous
#include <cuda_runtime.h>
#include <math.h>

// Problem dims (fixed for this problem instance)
#define N_TOK 32768
#define L_SEQ 512
#define B_ROWS 64
#define HDIM 768
#define EDIM 1000
#define PDIM 300
#define QLD  1024   // padded leading dim for Q

// ---------------- scratch (__device__ globals; no allocations allowed) ----------------
__device__ float g_means[(size_t)N_TOK * HDIM];  // segment means (reused across both label sets)
__device__ float g_P[EDIM * PDIM];               // proj_desc = ent @ w_desc   [E,P]
__device__ float g_Pt[PDIM * EDIM];              // transpose [P,E]
__device__ float g_Q[HDIM * QLD];                // Q = w_mention @ proj_desc^T  [H,E] ld=QLD
__device__ int   g_pred[N_TOK];                  // predicted labels
__device__ int   g_nzTok[N_TOK];                 // stream pos -> token index
__device__ int   g_cumB[N_TOK];                  // inclusive B-count by stream pos
__device__ int   g_segStart[N_TOK];              // start stream-pos per segment
__device__ int   g_outRow[N_TOK];                // segment -> output row (b*L + j)
__device__ int   g_c[2][B_ROWS];                 // per-row B counts, per set
__device__ int   g_hdr[3];                       // M (nonzero count), C (segment count), idx0

// ============================= fused MLP kernel =============================
// logits = relu(hidden @ w1 + b1) @ w2 + b2 ; write log_softmax + argmax
__global__ __launch_bounds__(256) void mlp_kernel(
    const float* __restrict__ hidden, const float* __restrict__ w1,
    const float* __restrict__ b1, const float* __restrict__ w2,
    const float* __restrict__ b2, float* __restrict__ out_logits)
{
    __shared__ float As[8][132];
    __shared__ float Bs[8][128];
    __shared__ float w2s[128][3];
    __shared__ float b1s[128];

    const int tid = threadIdx.x;
    const int tx = tid & 15, ty = tid >> 4;
    const int row0 = blockIdx.x * 128;

    float plog[8][3];
#pragma unroll
    for (int i = 0; i < 8; i++) { plog[i][0] = 0.f; plog[i][1] = 0.f; plog[i][2] = 0.f; }

    for (int jt = 0; jt < HDIM; jt += 128) {
        if (tid < 128) {
            b1s[tid]    = b1[jt + tid];
            w2s[tid][0] = w2[(jt + tid) * 3 + 0];
            w2s[tid][1] = w2[(jt + tid) * 3 + 1];
            w2s[tid][2] = w2[(jt + tid) * 3 + 2];
        }
        float acc[8][8];
#pragma unroll
        for (int i = 0; i < 8; i++)
#pragma unroll
            for (int j = 0; j < 8; j++) acc[i][j] = 0.f;

        for (int k0 = 0; k0 < HDIM; k0 += 8) {
            __syncthreads();
#pragma unroll
            for (int t = 0; t < 4; t++) {
                int e = tid + t * 256;
                int r = e >> 3, kk = e & 7;
                As[kk][r] = hidden[(size_t)(row0 + r) * HDIM + k0 + kk];
            }
#pragma unroll
            for (int t = 0; t < 4; t++) {
                int e = tid + t * 256;
                int kk = e >> 7, c = e & 127;
                Bs[kk][c] = w1[(size_t)(k0 + kk) * HDIM + jt + c];
            }
            __syncthreads();
#pragma unroll
            for (int kk = 0; kk < 8; kk++) {
                float ra[8], rb[8];
#pragma unroll
                for (int i = 0; i < 8; i++) ra[i] = As[kk][i * 16 + ty];
#pragma unroll
                for (int j = 0; j < 8; j++) rb[j] = Bs[kk][j * 16 + tx];
#pragma unroll
                for (int i = 0; i < 8; i++)
#pragma unroll
                    for (int j = 0; j < 8; j++) acc[i][j] += ra[i] * rb[j];
            }
        }
        __syncthreads();
#pragma unroll
        for (int j = 0; j < 8; j++) {
            int col = j * 16 + tx;
            float w20 = w2s[col][0], w21 = w2s[col][1], w22 = w2s[col][2];
            float bb = b1s[col];
#pragma unroll
            for (int i = 0; i < 8; i++) {
                float h = fmaxf(acc[i][j] + bb, 0.f);
                plog[i][0] += h * w20;
                plog[i][1] += h * w21;
                plog[i][2] += h * w22;
            }
        }
        __syncthreads();
    }
    // reduce over tx (16 lanes; rows depend only on ty)
#pragma unroll
    for (int i = 0; i < 8; i++)
#pragma unroll
        for (int k = 0; k < 3; k++) {
            float v = plog[i][k];
            v += __shfl_down_sync(0xffffffffu, v, 8, 16);
            v += __shfl_down_sync(0xffffffffu, v, 4, 16);
            v += __shfl_down_sync(0xffffffffu, v, 2, 16);
            v += __shfl_down_sync(0xffffffffu, v, 1, 16);
            plog[i][k] = v;
        }
    if (tx == 0) {
        float bb0 = b2[0], bb1 = b2[1], bb2 = b2[2];
#pragma unroll
        for (int i = 0; i < 8; i++) {
            int row = row0 + i * 16 + ty;
            float l0 = plog[i][0] + bb0;
            float l1 = plog[i][1] + bb1;
            float l2 = plog[i][2] + bb2;
            float m = fmaxf(l0, fmaxf(l1, l2));
            float lse = m + logf(expf(l0 - m) + expf(l1 - m) + expf(l2 - m));
            out_logits[(size_t)row * 3 + 0] = l0 - lse;
            out_logits[(size_t)row * 3 + 1] = l1 - lse;
            out_logits[(size_t)row * 3 + 2] = l2 - lse;
            int a = 0;
            if (l1 > l0) a = 1;
            float la = (a == 1) ? l1 : l0;
            if (l2 > la) a = 2;
            g_pred[row] = a;
        }
    }
}

// ============================= generic tiled GEMM =============================
// C[M,N] = A[M,K] @ B[K,N], row-major, guards everywhere.
// DYNM: effective M read from g_hdr[1] (=C). REMAP: output row via g_outRow.
template <bool DYNM, bool REMAP>
__global__ __launch_bounds__(256) void gemm_tiled(
    const float* __restrict__ A, const float* __restrict__ Bm, float* __restrict__ Cm,
    int M, int N, int K, int lda, int ldb, int ldc)
{
    __shared__ float As[8][132];
    __shared__ float Bs[8][128];
    const int tid = threadIdx.x;
    const int tx = tid & 15, ty = tid >> 4;
    const int row0 = blockIdx.y * 128, col0 = blockIdx.x * 128;
    const int Meff = DYNM ? g_hdr[1] : M;
    if (row0 >= Meff) return;

    float acc[8][8];
#pragma unroll
    for (int i = 0; i < 8; i++)
#pragma unroll
        for (int j = 0; j < 8; j++) acc[i][j] = 0.f;

    for (int k0 = 0; k0 < K; k0 += 8) {
        __syncthreads();
#pragma unroll
        for (int t = 0; t < 4; t++) {
            int e = tid + t * 256;
            int r = e >> 3, kk = e & 7;
            int gr = row0 + r, gk = k0 + kk;
            As[kk][r] = (gr < Meff && gk < K) ? A[(size_t)gr * lda + gk] : 0.f;
        }
#pragma unroll
        for (int t = 0; t < 4; t++) {
            int e = tid + t * 256;
            int kk = e >> 7, c = e & 127;
            int gk = k0 + kk, gc = col0 + c;
            Bs[kk][c] = (gk < K && gc < N) ? Bm[(size_t)gk * ldb + gc] : 0.f;
        }
        __syncthreads();
#pragma unroll
        for (int kk = 0; kk < 8; kk++) {
            float ra[8], rb[8];
#pragma unroll
            for (int i = 0; i < 8; i++) ra[i] = As[kk][i * 16 + ty];
#pragma unroll
            for (int j = 0; j < 8; j++) rb[j] = Bs[kk][j * 16 + tx];
#pragma unroll
            for (int i = 0; i < 8; i++)
#pragma unroll
                for (int j = 0; j < 8; j++) acc[i][j] += ra[i] * rb[j];
        }
    }
#pragma unroll
    for (int i = 0; i < 8; i++) {
        int r = row0 + i * 16 + ty;
        if (r >= Meff) continue;
        int orow = REMAP ? g_outRow[r] : r;
#pragma unroll
        for (int j = 0; j < 8; j++) {
            int c = col0 + j * 16 + tx;
            if (c < N) Cm[(size_t)orow * ldc + c] = acc[i][j];
        }
    }
}

// ============================= transpose (P -> Pt) =============================
__global__ void transpose_kernel(const float* __restrict__ P, float* __restrict__ Pt,
                                 int rows /*1000*/, int cols /*300*/)
{
    __shared__ float s[32][33];
    int c0 = blockIdx.x * 32, r0 = blockIdx.y * 32;
    int tx = threadIdx.x, ty = threadIdx.y;  // (32,8)
#pragma unroll
    for (int t = 0; t < 4; t++) {
        int r = r0 + ty + t * 8, c = c0 + tx;
        s[ty + t * 8][tx] = (r < rows && c < cols) ? P[(size_t)r * cols + c] : 0.f;
    }
    __syncthreads();
#pragma unroll
    for (int t = 0; t < 4; t++) {
        int r = c0 + ty + t * 8, c = r0 + tx;
        if (r < cols && c < rows) Pt[(size_t)r * rows + c] = s[tx][ty + t * 8];
    }
}

// ============================= scan kernel (1 block) =============================
// Faithfully reproduces the reference's sorted-stream / cumsum / idx0-shift logic.
__global__ void scan_kernel(const int* __restrict__ labels_in, int setIdx, int usePred)
{
    __shared__ int sNZ[1024], sB[1024];
    __shared__ int s_idx0;
    __shared__ int sC[B_ROWS], sSt[B_ROWS];
    const int* lab = usePred ? (const int*)g_pred : labels_in;
    const int tid = threadIdx.x;
    const int IPT = N_TOK / 1024;  // 32
    const int base = tid * IPT;

    int cn = 0, cb = 0;
    for (int t = 0; t < IPT; t++) {
        int l = lab[base + t];
        cn += (l != 0);
        cb += (l == 1);
    }
    sNZ[tid] = cn; sB[tid] = cb;
    if (tid == 0) s_idx0 = N_TOK;
    __syncthreads();
    if (tid == 0) {
        int an = 0, ab = 0;
        for (int t = 0; t < 1024; t++) {
            int n = sNZ[t], b = sB[t];
            sNZ[t] = an; sB[t] = ab;
            an += n; ab += b;
        }
        g_hdr[0] = an;  // M
        g_hdr[1] = ab;  // C
    }
    __syncthreads();
    const int M = g_hdr[0], C = g_hdr[1];
    int pn = sNZ[tid], pb = sB[tid];
    for (int t = 0; t < IPT; t++) {
        int i = base + t;
        int l = lab[i];
        if (l != 0) {
            if (l == 1) { pb++; atomicMin(&s_idx0, pn); }
            g_nzTok[pn] = i;
            g_cumB[pn] = pb;  // inclusive B-count at stream pos pn
            pn++;
        }
    }
    __syncthreads();
    const int idx0 = (C > 0) ? s_idx0 : 0;
    if (tid == 0) g_hdr[2] = idx0;
    // segment starts: seg(p) is nondecreasing, steps <=1, seg(0)=0, seg(M-1)=C-1
    if (C > 0) {
        for (int p = tid; p < M; p += 1024) {
            int q = min(p + idx0, N_TOK - 1);
            int s = ((q < M) ? g_cumB[q] : C) - 1;
            if (p == 0) {
                g_segStart[0] = 0;
            } else {
                int q2 = min(p - 1 + idx0, N_TOK - 1);
                int s2 = ((q2 < M) ? g_cumB[q2] : C) - 1;
                if (s != s2) g_segStart[s] = p;
            }
        }
    }
    // per-row B counts + output row mapping
    if (tid < B_ROWS) {
        int cnt = 0;
        for (int l = 0; l < L_SEQ; l++) cnt += (lab[tid * L_SEQ + l] == 1);
        sC[tid] = cnt;
    }
    __syncthreads();
    if (tid == 0) {
        int a = 0;
        for (int b = 0; b < B_ROWS; b++) { sSt[b] = a; a += sC[b]; }
    }
    __syncthreads();
    if (tid < B_ROWS) {
        g_c[setIdx][tid] = sC[tid];
        int st = sSt[tid];
        for (int j = 0; j < sC[tid]; j++) g_outRow[st + j] = tid * L_SEQ + j;
    }
}

// ============================= segment means =============================
__global__ void means_kernel(const float* __restrict__ hidden)
{
    const int C = g_hdr[1], M = g_hdr[0];
    const int tid = threadIdx.x;  // 256 threads, HDIM = 3*256
    for (int s = blockIdx.x; s < C; s += gridDim.x) {
        int st = g_segStart[s];
        int en = (s + 1 < C) ? g_segStart[s + 1] : M;
        float a0 = 0.f, a1 = 0.f, a2 = 0.f;
        for (int p = st; p < en; p++) {
            const float* h = hidden + (size_t)g_nzTok[p] * HDIM;
            a0 += h[tid];
            a1 += h[tid + 256];
            a2 += h[tid + 512];
        }
        float inv = 1.f / (float)(en - st);
        float* m = g_means + (size_t)s * HDIM;
        m[tid] = a0 * inv;
        m[tid + 256] = a1 * inv;
        m[tid + 512] = a2 * inv;
    }
}

// ============================= row-wise log-softmax over E =============================
__global__ void softmax_kernel(float* __restrict__ scores)  // both sets
{
    __shared__ float red[256];
    const int gid = blockIdx.x;
    const int set = gid >> 15;           // /N_TOK
    const int r = gid & (N_TOK - 1);
    const int b = r / L_SEQ, j = r - b * L_SEQ;
    float* row = scores + (size_t)set * N_TOK * EDIM + (size_t)r * EDIM;
    const int tid = threadIdx.x;
    const int NV = EDIM / 4;  // 250

    if (j >= g_c[set][b]) {
        const float c = -6.9077552789821368f;  // -log(1000): log_softmax of zero logits
        if (tid < NV) reinterpret_cast<float4*>(row)[tid] = make_float4(c, c, c, c);
        return;
    }
    float4 v = make_float4(0.f, 0.f, 0.f, 0.f);
    float m = -3.0e38f;
    if (tid < NV) {
        v = reinterpret_cast<const float4*>(row)[tid];
        m = fmaxf(fmaxf(v.x, v.y), fmaxf(v.z, v.w));
    }
    red[tid] = m;
    __syncthreads();
    for (int s = 128; s > 0; s >>= 1) {
        if (tid < s) red[tid] = fmaxf(red[tid], red[tid + s]);
        __syncthreads();
    }
    float vmax = red[0];
    __syncthreads();
    float se = 0.f;
    if (tid < NV)
        se = expf(v.x - vmax) + expf(v.y - vmax) + expf(v.z - vmax) + expf(v.w - vmax);
    red[tid] = se;
    __syncthreads();
    for (int s = 128; s > 0; s >>= 1) {
        if (tid < s) red[tid] += red[tid + s];
        __syncthreads();
    }
    float lse = vmax + logf(red[0]);
    if (tid < NV) {
        v.x -= lse; v.y -= lse; v.z -= lse; v.w -= lse;
        reinterpret_cast<float4*>(row)[tid] = v;
    }
}

// ============================= launch =============================
extern "C" void kernel_launch(void* const* d_in, const int* in_sizes, int n_in,
                              void* d_out, int out_size)
{
    const int*   labels    = (const int*)d_in[0];
    const float* hidden    = (const float*)d_in[1];
    const float* ent       = (const float*)d_in[2];
    const float* w1        = (const float*)d_in[3];
    const float* b1        = (const float*)d_in[4];
    const float* w2        = (const float*)d_in[5];
    const float* b2        = (const float*)d_in[6];
    const float* w_mention = (const float*)d_in[7];
    const float* w_desc    = (const float*)d_in[8];
    float* out = (float*)d_out;

    void *pP, *pPt, *pQ, *pMeans;
    cudaGetSymbolAddress(&pP, g_P);
    cudaGetSymbolAddress(&pPt, g_Pt);
    cudaGetSymbolAddress(&pQ, g_Q);
    cudaGetSymbolAddress(&pMeans, g_means);

    // 1. fused MLP: bio_slot_logits (out[0:N*3]) + predicted labels
    mlp_kernel<<<N_TOK / 128, 256>>>(hidden, w1, b1, w2, b2, out);

    // 2. Q = w_mention @ (ent @ w_desc)^T
    gemm_tiled<false, false><<<dim3((PDIM + 127) / 128, (EDIM + 127) / 128), 256>>>(
        ent, w_desc, (float*)pP, EDIM, PDIM, HDIM, HDIM, PDIM, PDIM);
    transpose_kernel<<<dim3((PDIM + 31) / 32, (EDIM + 31) / 32), dim3(32, 8)>>>(
        (const float*)pP, (float*)pPt, EDIM, PDIM);
    gemm_tiled<false, false><<<dim3((EDIM + 127) / 128, (HDIM + 127) / 128), 256>>>(
        w_mention, (const float*)pPt, (float*)pQ, HDIM, EDIM, PDIM, PDIM, EDIM, QLD);

    float* score_base = out + (size_t)N_TOK * 3;

    // 3. per label set: scan -> segment means -> dot GEMM (writes into mapped out rows)
    for (int set = 0; set < 2; set++) {
        scan_kernel<<<1, 1024>>>(labels, set, set /*usePred*/);
        means_kernel<<<4096, 256>>>(hidden);
        gemm_tiled<true, true><<<dim3((EDIM + 127) / 128, N_TOK / 128), 256>>>(
            (const float*)pMeans, (const float*)pQ,
            score_base + (size_t)set * N_TOK * EDIM,
            N_TOK, EDIM, HDIM, HDIM, QLD, EDIM);
    }

    // 4. log-softmax over E for all rows (valid in-place; invalid -> -log(E))
    softmax_kernel<<<2 * N_TOK, 256>>>(score_base);
}

// round 4
// speedup vs baseline: 1.4348x; 1.4301x over previous
#include <cuda_runtime.h>
#include <math.h>
#include <stdint.h>

// Problem dims
#define N_TOK 32768
#define L_SEQ 512
#define B_ROWS 64
#define HDIM 768
#define EDIM 1000
#define PDIM 300

// ---------------- scratch ----------------
__device__ float g_means[(size_t)N_TOK * HDIM];
__device__ float g_h1[(size_t)N_TOK * HDIM];
__device__ float g_P[EDIM * PDIM];
__device__ float g_w1t[HDIM * HDIM];
__device__ float g_wdT[PDIM * HDIM];
__device__ float g_Qt[1024 * HDIM];              // rows 1000..1023 stay zero (zero-initialized, never written)
__device__ int   g_pred[N_TOK];
__device__ int   g_nzTok[N_TOK];
__device__ int   g_cumB[N_TOK];
__device__ int   g_segStart[N_TOK];
__device__ int   g_outRow[N_TOK];
__device__ int   g_c[2][B_ROWS];
__device__ int   g_hdr[3];

// ======================= tf32 helpers =======================
__device__ __forceinline__ uint32_t f2tf32(float a) {
    uint32_t u;
    asm("cvt.rna.tf32.f32 %0, %1;" : "=r"(u) : "f"(a));
    return u;
}

#define MMA_TF32(d, a, b) \
    asm volatile("mma.sync.aligned.m16n8k8.row.col.f32.tf32.tf32.f32 " \
        "{%0,%1,%2,%3}, {%4,%5,%6,%7}, {%8,%9}, {%0,%1,%2,%3};" \
        : "+f"((d)[0]), "+f"((d)[1]), "+f"((d)[2]), "+f"((d)[3]) \
        : "r"((a)[0]), "r"((a)[1]), "r"((a)[2]), "r"((a)[3]), "r"((b)[0]), "r"((b)[1]))

// SMEM tile layout: [128 rows][36 (32 + pad 4) k-cols] of uint32 (tf32 bits)
#define TLD 36
#define TILE_U32 (128 * TLD)
#define GEMM_SMEM_DYN (4 * TILE_U32 * 4)   // AH, AL, BH, BL = 73728 bytes

// Load 128x32 fp32 K-major tile from global, split into tf32 hi/lo in SMEM.
__device__ __forceinline__ void load_tile(
    const float* __restrict__ src, int rbase, int rmax, int ld, int K, int kbase,
    uint32_t* __restrict__ hi, uint32_t* __restrict__ lo, int tid)
{
#pragma unroll
    for (int i = 0; i < 4; i++) {
        int idx = i * 256 + tid;
        int r = idx >> 3, q = idx & 7;
        int gr = rbase + r, gk = kbase + q * 4;
        float4 v = make_float4(0.f, 0.f, 0.f, 0.f);
        if (gr < rmax && gk + 4 <= K)
            v = *reinterpret_cast<const float4*>(src + (size_t)gr * ld + gk);
        uint32_t hx = f2tf32(v.x), hy = f2tf32(v.y), hz = f2tf32(v.z), hw = f2tf32(v.w);
        uint32_t lx = f2tf32(v.x - __uint_as_float(hx));
        uint32_t ly = f2tf32(v.y - __uint_as_float(hy));
        uint32_t lz = f2tf32(v.z - __uint_as_float(hz));
        uint32_t lw = f2tf32(v.w - __uint_as_float(hw));
        int off = r * TLD + q * 4;                          // *4B => 144r+16q, 16B aligned
        *reinterpret_cast<uint4*>(hi + off) = make_uint4(hx, hy, hz, hw);
        *reinterpret_cast<uint4*>(lo + off) = make_uint4(lx, ly, lz, lw);
    }
}

// ======================= 3xTF32 mma.sync GEMM =======================
// D[M,N] = A[M,K] @ B[NB,K]^T (both row-major, K contiguous).
// MODE: 0 plain, 1 bias+relu, 2 dynamic-M (g_hdr[1]) + row remap (g_outRow).
template <int MODE>
__global__ __launch_bounds__(256, 1) void tc_gemm(
    const float* __restrict__ A, const float* __restrict__ Bm, float* __restrict__ Cm,
    const float* __restrict__ bias, int M, int N, int NB, int K, int lda, int ldb, int ldc)
{
    extern __shared__ uint32_t sm[];
    uint32_t* AH = sm;
    uint32_t* AL = sm + TILE_U32;
    uint32_t* BH = sm + 2 * TILE_U32;
    uint32_t* BL = sm + 3 * TILE_U32;

    const int tid = threadIdx.x;
    const int wid = tid >> 5, lane = tid & 31;
    const int g = lane >> 2, t4 = lane & 3;
    const int wm = wid & 3;        // 0..3  -> 32 rows each
    const int wn = wid >> 2;       // 0..1  -> 64 cols each
    const int row0 = blockIdx.y * 128, col0 = blockIdx.x * 128;
    const int Meff = (MODE == 2) ? g_hdr[1] : M;
    if (row0 >= Meff) return;

    float acc[2][8][4];
#pragma unroll
    for (int mt = 0; mt < 2; mt++)
#pragma unroll
        for (int nt = 0; nt < 8; nt++)
#pragma unroll
            for (int c = 0; c < 4; c++) acc[mt][nt][c] = 0.f;

    const int KTILES = (K + 31) >> 5;

    for (int kt = 0; kt < KTILES; kt++) {
        __syncthreads();
        load_tile(A, row0, Meff, lda, K, kt << 5, AH, AL, tid);
        load_tile(Bm, col0, NB, ldb, K, kt << 5, BH, BL, tid);
        __syncthreads();
#pragma unroll
        for (int kk = 0; kk < 4; kk++) {
            const int kb = kk * 8;
            uint32_t ah[2][4], al[2][4];
#pragma unroll
            for (int mt = 0; mt < 2; mt++) {
                int R = (wm * 32 + mt * 16 + g) * TLD + kb + t4;
                ah[mt][0] = AH[R];
                ah[mt][1] = AH[R + 8 * TLD];
                ah[mt][2] = AH[R + 4];
                ah[mt][3] = AH[R + 8 * TLD + 4];
                al[mt][0] = AL[R];
                al[mt][1] = AL[R + 8 * TLD];
                al[mt][2] = AL[R + 4];
                al[mt][3] = AL[R + 8 * TLD + 4];
            }
            uint32_t bh[8][2], bl[8][2];
#pragma unroll
            for (int nt = 0; nt < 8; nt++) {
                int Cb = (wn * 64 + nt * 8 + g) * TLD + kb + t4;
                bh[nt][0] = BH[Cb];
                bh[nt][1] = BH[Cb + 4];
                bl[nt][0] = BL[Cb];
                bl[nt][1] = BL[Cb + 4];
            }
#pragma unroll
            for (int mt = 0; mt < 2; mt++)
#pragma unroll
                for (int nt = 0; nt < 8; nt++) MMA_TF32(acc[mt][nt], ah[mt], bh[nt]);
#pragma unroll
            for (int mt = 0; mt < 2; mt++)
#pragma unroll
                for (int nt = 0; nt < 8; nt++) MMA_TF32(acc[mt][nt], al[mt], bh[nt]);
#pragma unroll
            for (int mt = 0; mt < 2; mt++)
#pragma unroll
                for (int nt = 0; nt < 8; nt++) MMA_TF32(acc[mt][nt], ah[mt], bl[nt]);
        }
    }

    // epilogue: register accs -> global
#pragma unroll
    for (int mt = 0; mt < 2; mt++) {
        int rA = row0 + wm * 32 + mt * 16 + g;
        int rB = rA + 8;
        bool vA = rA < Meff, vB = rB < Meff;
        int oA = 0, oB = 0;
        if (MODE == 2) {
            if (vA) oA = g_outRow[rA];
            if (vB) oB = g_outRow[rB];
        } else { oA = rA; oB = rB; }
#pragma unroll
        for (int nt = 0; nt < 8; nt++) {
            int c0 = col0 + wn * 64 + nt * 8 + 2 * t4;
            int c1 = c0 + 1;
            float v0 = acc[mt][nt][0], v1 = acc[mt][nt][1];
            float v2 = acc[mt][nt][2], v3 = acc[mt][nt][3];
            if (MODE == 1) {
                float bb0 = (c0 < N) ? bias[c0] : 0.f;
                float bb1 = (c1 < N) ? bias[c1] : 0.f;
                v0 = fmaxf(v0 + bb0, 0.f); v1 = fmaxf(v1 + bb1, 0.f);
                v2 = fmaxf(v2 + bb0, 0.f); v3 = fmaxf(v3 + bb1, 0.f);
            }
            if (vA) {
                if (c0 < N) Cm[(size_t)oA * ldc + c0] = v0;
                if (c1 < N) Cm[(size_t)oA * ldc + c1] = v1;
            }
            if (vB) {
                if (c0 < N) Cm[(size_t)oB * ldc + c0] = v2;
                if (c1 < N) Cm[(size_t)oB * ldc + c1] = v3;
            }
        }
    }
}

// ======================= second MLP layer + log-softmax + argmax =======================
__global__ __launch_bounds__(256) void mlp2_kernel(
    const float* __restrict__ h1, const float* __restrict__ w2,
    const float* __restrict__ b2, float* __restrict__ out_logits)
{
    __shared__ float w2s[HDIM * 3];
    for (int i = threadIdx.x; i < HDIM * 3; i += 256) w2s[i] = w2[i];
    __syncthreads();
    int warp = threadIdx.x >> 5, lid = threadIdx.x & 31;
    int row = blockIdx.x * 8 + warp;
    const float* hr = h1 + (size_t)row * HDIM;
    float a0 = 0.f, a1 = 0.f, a2 = 0.f;
    for (int k = lid; k < HDIM; k += 32) {
        float h = hr[k];
        a0 += h * w2s[k * 3 + 0];
        a1 += h * w2s[k * 3 + 1];
        a2 += h * w2s[k * 3 + 2];
    }
#pragma unroll
    for (int s = 16; s > 0; s >>= 1) {
        a0 += __shfl_down_sync(0xffffffffu, a0, s);
        a1 += __shfl_down_sync(0xffffffffu, a1, s);
        a2 += __shfl_down_sync(0xffffffffu, a2, s);
    }
    if (lid == 0) {
        float l0 = a0 + b2[0], l1 = a1 + b2[1], l2 = a2 + b2[2];
        float m = fmaxf(l0, fmaxf(l1, l2));
        float lse = m + logf(expf(l0 - m) + expf(l1 - m) + expf(l2 - m));
        out_logits[(size_t)row * 3 + 0] = l0 - lse;
        out_logits[(size_t)row * 3 + 1] = l1 - lse;
        out_logits[(size_t)row * 3 + 2] = l2 - lse;
        int a = 0;
        if (l1 > l0) a = 1;
        float la = (a == 1) ? l1 : l0;
        if (l2 > la) a = 2;
        g_pred[row] = a;
    }
}

// ======================= transpose =======================
__global__ void transpose_kernel(const float* __restrict__ P, float* __restrict__ Pt,
                                 int rows, int cols)
{
    __shared__ float s[32][33];
    int c0 = blockIdx.x * 32, r0 = blockIdx.y * 32;
    int tx = threadIdx.x, ty = threadIdx.y;
#pragma unroll
    for (int t = 0; t < 4; t++) {
        int r = r0 + ty + t * 8, c = c0 + tx;
        s[ty + t * 8][tx] = (r < rows && c < cols) ? P[(size_t)r * cols + c] : 0.f;
    }
    __syncthreads();
#pragma unroll
    for (int t = 0; t < 4; t++) {
        int r = c0 + ty + t * 8, c = r0 + tx;
        if (r < cols && c < rows) Pt[(size_t)r * rows + c] = s[tx][ty + t * 8];
    }
}

// ======================= scan kernel (1 block) =======================
__global__ void scan_kernel(const int* __restrict__ labels_in, int setIdx, int usePred)
{
    __shared__ int sNZ[1024], sB[1024];
    __shared__ int s_idx0;
    __shared__ int sC[B_ROWS], sSt[B_ROWS];
    const int* lab = usePred ? (const int*)g_pred : labels_in;
    const int tid = threadIdx.x;
    const int IPT = N_TOK / 1024;
    const int base = tid * IPT;

    int cn = 0, cb = 0;
    for (int t = 0; t < IPT; t++) {
        int l = lab[base + t];
        cn += (l != 0);
        cb += (l == 1);
    }
    sNZ[tid] = cn; sB[tid] = cb;
    if (tid == 0) s_idx0 = N_TOK;
    __syncthreads();
    if (tid == 0) {
        int an = 0, ab = 0;
        for (int t = 0; t < 1024; t++) {
            int n = sNZ[t], b = sB[t];
            sNZ[t] = an; sB[t] = ab;
            an += n; ab += b;
        }
        g_hdr[0] = an;
        g_hdr[1] = ab;
    }
    __syncthreads();
    const int M = g_hdr[0], C = g_hdr[1];
    int pn = sNZ[tid], pb = sB[tid];
    for (int t = 0; t < IPT; t++) {
        int i = base + t;
        int l = lab[i];
        if (l != 0) {
            if (l == 1) { pb++; atomicMin(&s_idx0, pn); }
            g_nzTok[pn] = i;
            g_cumB[pn] = pb;
            pn++;
        }
    }
    __syncthreads();
    const int idx0 = (C > 0) ? s_idx0 : 0;
    if (tid == 0) g_hdr[2] = idx0;
    if (C > 0) {
        for (int p = tid; p < M; p += 1024) {
            int q = min(p + idx0, N_TOK - 1);
            int s = ((q < M) ? g_cumB[q] : C) - 1;
            if (p == 0) {
                g_segStart[0] = 0;
            } else {
                int q2 = min(p - 1 + idx0, N_TOK - 1);
                int s2 = ((q2 < M) ? g_cumB[q2] : C) - 1;
                if (s != s2) g_segStart[s] = p;
            }
        }
    }
    if (tid < B_ROWS) {
        int cnt = 0;
        for (int l = 0; l < L_SEQ; l++) cnt += (lab[tid * L_SEQ + l] == 1);
        sC[tid] = cnt;
    }
    __syncthreads();
    if (tid == 0) {
        int a = 0;
        for (int b = 0; b < B_ROWS; b++) { sSt[b] = a; a += sC[b]; }
    }
    __syncthreads();
    if (tid < B_ROWS) {
        g_c[setIdx][tid] = sC[tid];
        int st = sSt[tid];
        for (int j = 0; j < sC[tid]; j++) g_outRow[st + j] = tid * L_SEQ + j;
    }
}

// ======================= segment means =======================
__global__ void means_kernel(const float* __restrict__ hidden)
{
    const int C = g_hdr[1], M = g_hdr[0];
    const int tid = threadIdx.x;
    for (int s = blockIdx.x; s < C; s += gridDim.x) {
        int st = g_segStart[s];
        int en = (s + 1 < C) ? g_segStart[s + 1] : M;
        float a0 = 0.f, a1 = 0.f, a2 = 0.f;
        for (int p = st; p < en; p++) {
            const float* h = hidden + (size_t)g_nzTok[p] * HDIM;
            a0 += h[tid];
            a1 += h[tid + 256];
            a2 += h[tid + 512];
        }
        float inv = 1.f / (float)(en - st);
        float* m = g_means + (size_t)s * HDIM;
        m[tid] = a0 * inv;
        m[tid + 256] = a1 * inv;
        m[tid + 512] = a2 * inv;
    }
}

// ======================= row-wise log-softmax over E =======================
__global__ void softmax_kernel(float* __restrict__ scores)
{
    __shared__ float red[256];
    const int gid = blockIdx.x;
    const int set = gid >> 15;
    const int r = gid & (N_TOK - 1);
    const int b = r / L_SEQ, j = r - b * L_SEQ;
    float* row = scores + (size_t)set * N_TOK * EDIM + (size_t)r * EDIM;
    const int tid = threadIdx.x;
    const int NV = EDIM / 4;

    if (j >= g_c[set][b]) {
        const float c = -6.9077552789821368f;
        if (tid < NV) reinterpret_cast<float4*>(row)[tid] = make_float4(c, c, c, c);
        return;
    }
    float4 v = make_float4(0.f, 0.f, 0.f, 0.f);
    float m = -3.0e38f;
    if (tid < NV) {
        v = reinterpret_cast<const float4*>(row)[tid];
        m = fmaxf(fmaxf(v.x, v.y), fmaxf(v.z, v.w));
    }
    red[tid] = m;
    __syncthreads();
    for (int s = 128; s > 0; s >>= 1) {
        if (tid < s) red[tid] = fmaxf(red[tid], red[tid + s]);
        __syncthreads();
    }
    float vmax = red[0];
    __syncthreads();
    float se = 0.f;
    if (tid < NV)
        se = expf(v.x - vmax) + expf(v.y - vmax) + expf(v.z - vmax) + expf(v.w - vmax);
    red[tid] = se;
    __syncthreads();
    for (int s = 128; s > 0; s >>= 1) {
        if (tid < s) red[tid] += red[tid + s];
        __syncthreads();
    }
    float lse = vmax + logf(red[0]);
    if (tid < NV) {
        v.x -= lse; v.y -= lse; v.z -= lse; v.w -= lse;
        reinterpret_cast<float4*>(row)[tid] = v;
    }
}

// ======================= launch =======================
extern "C" void kernel_launch(void* const* d_in, const int* in_sizes, int n_in,
                              void* d_out, int out_size)
{
    const int*   labels    = (const int*)d_in[0];
    const float* hidden    = (const float*)d_in[1];
    const float* ent       = (const float*)d_in[2];
    const float* w1        = (const float*)d_in[3];
    const float* b1        = (const float*)d_in[4];
    const float* w2        = (const float*)d_in[5];
    const float* b2        = (const float*)d_in[6];
    const float* w_mention = (const float*)d_in[7];
    const float* w_desc    = (const float*)d_in[8];
    float* out = (float*)d_out;

    cudaFuncSetAttribute(tc_gemm<0>, cudaFuncAttributeMaxDynamicSharedMemorySize, GEMM_SMEM_DYN);
    cudaFuncSetAttribute(tc_gemm<1>, cudaFuncAttributeMaxDynamicSharedMemorySize, GEMM_SMEM_DYN);
    cudaFuncSetAttribute(tc_gemm<2>, cudaFuncAttributeMaxDynamicSharedMemorySize, GEMM_SMEM_DYN);

    void *pP, *pQt, *pMeans, *pH1, *pW1t, *pWdT;
    cudaGetSymbolAddress(&pP, g_P);
    cudaGetSymbolAddress(&pQt, g_Qt);
    cudaGetSymbolAddress(&pMeans, g_means);
    cudaGetSymbolAddress(&pH1, g_h1);
    cudaGetSymbolAddress(&pW1t, g_w1t);
    cudaGetSymbolAddress(&pWdT, g_wdT);

    // transposes: w1t = w1^T [768x768], wdT = w_desc^T [300x768]
    transpose_kernel<<<dim3(24, 24), dim3(32, 8)>>>(w1, (float*)pW1t, HDIM, HDIM);
    transpose_kernel<<<dim3(10, 24), dim3(32, 8)>>>(w_desc, (float*)pWdT, HDIM, PDIM);

    // h1 = relu(hidden @ w1 + b1)   [32768 x 768]
    tc_gemm<1><<<dim3(6, 256), 256, GEMM_SMEM_DYN>>>(
        hidden, (const float*)pW1t, (float*)pH1, b1,
        N_TOK, HDIM, HDIM, HDIM, HDIM, HDIM, HDIM);

    // logits + argmax
    mlp2_kernel<<<N_TOK / 8, 256>>>((const float*)pH1, w2, b2, out);

    // P = ent @ w_desc   [1000 x 300]
    tc_gemm<0><<<dim3(3, 8), 256, GEMM_SMEM_DYN>>>(
        ent, (const float*)pWdT, (float*)pP, nullptr,
        EDIM, PDIM, PDIM, HDIM, HDIM, HDIM, PDIM);

    // Qt = P @ w_mention^T   [1000 x 768]  (B = w_mention [768 x 300] K-major directly)
    tc_gemm<0><<<dim3(6, 8), 256, GEMM_SMEM_DYN>>>(
        (const float*)pP, w_mention, (float*)pQt, nullptr,
        EDIM, HDIM, HDIM, PDIM, PDIM, PDIM, HDIM);

    float* score_base = out + (size_t)N_TOK * 3;

    for (int set = 0; set < 2; set++) {
        scan_kernel<<<1, 1024>>>(labels, set, set);
        means_kernel<<<4096, 256>>>(hidden);
        // scores = means @ Qt^T  -> remapped rows of out
        tc_gemm<2><<<dim3(8, 256), 256, GEMM_SMEM_DYN>>>(
            (const float*)pMeans, (const float*)pQt,
            score_base + (size_t)set * N_TOK * EDIM, nullptr,
            N_TOK, EDIM, 1024, HDIM, HDIM, HDIM, EDIM);
    }

    softmax_kernel<<<2 * N_TOK, 256>>>(score_base);
}

// round 5
// speedup vs baseline: 1.8931x; 1.3194x over previous
#include <cuda_runtime.h>
#include <cuda_bf16.h>
#include <math.h>
#include <stdint.h>

// Problem dims
#define N_TOK 32768
#define L_SEQ 512
#define B_ROWS 64
#define HDIM 768
#define EDIM 1000
#define PDIM 300

// ---------------- scratch ----------------
__device__ float g_means[(size_t)N_TOK * HDIM];
__device__ float g_h1[(size_t)N_TOK * HDIM];
__device__ float g_P[EDIM * PDIM];
__device__ float g_w1t[HDIM * HDIM];
__device__ float g_wdT[PDIM * HDIM];
__device__ float g_Qt[1024 * HDIM];              // rows 1000..1023 stay zero (never written)
__device__ int   g_pred[N_TOK];
__device__ int   g_nzTok[N_TOK];
__device__ int   g_cumB[N_TOK];
__device__ int   g_segStart[N_TOK];
__device__ int   g_outRow[N_TOK];
__device__ int   g_c[2][B_ROWS];
__device__ int   g_hdr[3];

// ======================= dtype helpers =======================
__device__ __forceinline__ uint32_t f2tf32(float a) {
    uint32_t u;
    asm("cvt.rna.tf32.f32 %0, %1;" : "=r"(u) : "f"(a));
    return u;
}
__device__ __forceinline__ void split_bf16_pair(float x, float y, uint32_t& hi, uint32_t& lo) {
    __nv_bfloat162 h2 = __float22bfloat162_rn(make_float2(x, y));
    uint32_t hb = *reinterpret_cast<uint32_t*>(&h2);       // low16=bf16(x), high16=bf16(y)
    float hx = __uint_as_float(hb << 16);
    float hy = __uint_as_float(hb & 0xffff0000u);
    __nv_bfloat162 l2 = __float22bfloat162_rn(make_float2(x - hx, y - hy));
    hi = hb;
    lo = *reinterpret_cast<uint32_t*>(&l2);
}

#define MMA_TF32(d, a, b) \
    asm volatile("mma.sync.aligned.m16n8k8.row.col.f32.tf32.tf32.f32 " \
        "{%0,%1,%2,%3}, {%4,%5,%6,%7}, {%8,%9}, {%0,%1,%2,%3};" \
        : "+f"((d)[0]), "+f"((d)[1]), "+f"((d)[2]), "+f"((d)[3]) \
        : "r"((a)[0]), "r"((a)[1]), "r"((a)[2]), "r"((a)[3]), "r"((b)[0]), "r"((b)[1]))

#define MMA_BF16(d, a, b) \
    asm volatile("mma.sync.aligned.m16n8k16.row.col.f32.bf16.bf16.f32 " \
        "{%0,%1,%2,%3}, {%4,%5,%6,%7}, {%8,%9}, {%0,%1,%2,%3};" \
        : "+f"((d)[0]), "+f"((d)[1]), "+f"((d)[2]), "+f"((d)[3]) \
        : "r"((a)[0]), "r"((a)[1]), "r"((a)[2]), "r"((a)[3]), "r"((b)[0]), "r"((b)[1]))

// SMEM strides (uint32 units)
#define TLD32 36   // tf32: 32 floats + pad4 per row
#define TLD16 20   // bf16: 16 packed u32 + pad4 per row

// ======================= global -> register tile prefetch =======================
__device__ __forceinline__ void ldg_tile(
    const float* __restrict__ src, int rbase, int rmax, int ld, int K, int kbase,
    float4* p, int tid)
{
#pragma unroll
    for (int i = 0; i < 4; i++) {
        int idx = i * 256 + tid;
        int r = idx >> 3, q = idx & 7;
        int gr = rbase + r, gk = kbase + q * 4;
        float4 v = make_float4(0.f, 0.f, 0.f, 0.f);
        if (gr < rmax && gk + 4 <= K)
            v = *reinterpret_cast<const float4*>(src + (size_t)gr * ld + gk);
        p[i] = v;
    }
}

// ======================= register tile -> SMEM (with split) =======================
template <int DT>
__device__ __forceinline__ void sts_tile(uint32_t* st, const float4* pa, const float4* pb, int tid)
{
    if (DT == 0) {
        uint32_t* Ah = st;
        uint32_t* Al = st + 128 * TLD32;
        uint32_t* Bh = st + 2 * 128 * TLD32;
        uint32_t* Bl = st + 3 * 128 * TLD32;
#pragma unroll
        for (int i = 0; i < 4; i++) {
            int idx = i * 256 + tid;
            int off = (idx >> 3) * TLD32 + (idx & 7) * 4;
            float4 va = pa[i], vb = pb[i];
            uint32_t hx = f2tf32(va.x), hy = f2tf32(va.y), hz = f2tf32(va.z), hw = f2tf32(va.w);
            *reinterpret_cast<uint4*>(Ah + off) = make_uint4(hx, hy, hz, hw);
            *reinterpret_cast<uint4*>(Al + off) = make_uint4(
                f2tf32(va.x - __uint_as_float(hx)), f2tf32(va.y - __uint_as_float(hy)),
                f2tf32(va.z - __uint_as_float(hz)), f2tf32(va.w - __uint_as_float(hw)));
            hx = f2tf32(vb.x); hy = f2tf32(vb.y); hz = f2tf32(vb.z); hw = f2tf32(vb.w);
            *reinterpret_cast<uint4*>(Bh + off) = make_uint4(hx, hy, hz, hw);
            *reinterpret_cast<uint4*>(Bl + off) = make_uint4(
                f2tf32(vb.x - __uint_as_float(hx)), f2tf32(vb.y - __uint_as_float(hy)),
                f2tf32(vb.z - __uint_as_float(hz)), f2tf32(vb.w - __uint_as_float(hw)));
        }
    } else {
        uint32_t* Ah = st;
        uint32_t* Al = st + 128 * TLD16;
        uint32_t* Bh = st + 2 * 128 * TLD16;
        uint32_t* Bl = st + 3 * 128 * TLD16;
#pragma unroll
        for (int i = 0; i < 4; i++) {
            int idx = i * 256 + tid;
            int off = (idx >> 3) * TLD16 + (idx & 7) * 2;
            float4 va = pa[i], vb = pb[i];
            uint32_t h0, l0, h1, l1;
            split_bf16_pair(va.x, va.y, h0, l0);
            split_bf16_pair(va.z, va.w, h1, l1);
            *reinterpret_cast<uint2*>(Ah + off) = make_uint2(h0, h1);
            *reinterpret_cast<uint2*>(Al + off) = make_uint2(l0, l1);
            split_bf16_pair(vb.x, vb.y, h0, l0);
            split_bf16_pair(vb.z, vb.w, h1, l1);
            *reinterpret_cast<uint2*>(Bh + off) = make_uint2(h0, h1);
            *reinterpret_cast<uint2*>(Bl + off) = make_uint2(l0, l1);
        }
    }
}

// ======================= compute one K=32 tile =======================
template <int DT>
__device__ __forceinline__ void compute_tile(
    const uint32_t* st, float acc[2][8][4], int wm, int wn, int g, int t4)
{
    if (DT == 0) {
        const uint32_t* AH = st;
        const uint32_t* AL = st + 128 * TLD32;
        const uint32_t* BH = st + 2 * 128 * TLD32;
        const uint32_t* BL = st + 3 * 128 * TLD32;
#pragma unroll
        for (int kk = 0; kk < 4; kk++) {
            const int kb = kk * 8;
            uint32_t ah[2][4], al[2][4];
#pragma unroll
            for (int mt = 0; mt < 2; mt++) {
                int R = (wm * 32 + mt * 16 + g) * TLD32 + kb + t4;
                ah[mt][0] = AH[R];              ah[mt][1] = AH[R + 8 * TLD32];
                ah[mt][2] = AH[R + 4];          ah[mt][3] = AH[R + 8 * TLD32 + 4];
                al[mt][0] = AL[R];              al[mt][1] = AL[R + 8 * TLD32];
                al[mt][2] = AL[R + 4];          al[mt][3] = AL[R + 8 * TLD32 + 4];
            }
            uint32_t bh[8][2], bl[8][2];
#pragma unroll
            for (int nt = 0; nt < 8; nt++) {
                int Cb = (wn * 64 + nt * 8 + g) * TLD32 + kb + t4;
                bh[nt][0] = BH[Cb]; bh[nt][1] = BH[Cb + 4];
                bl[nt][0] = BL[Cb]; bl[nt][1] = BL[Cb + 4];
            }
#pragma unroll
            for (int mt = 0; mt < 2; mt++)
#pragma unroll
                for (int nt = 0; nt < 8; nt++) MMA_TF32(acc[mt][nt], ah[mt], bh[nt]);
#pragma unroll
            for (int mt = 0; mt < 2; mt++)
#pragma unroll
                for (int nt = 0; nt < 8; nt++) MMA_TF32(acc[mt][nt], al[mt], bh[nt]);
#pragma unroll
            for (int mt = 0; mt < 2; mt++)
#pragma unroll
                for (int nt = 0; nt < 8; nt++) MMA_TF32(acc[mt][nt], ah[mt], bl[nt]);
        }
    } else {
        const uint32_t* AH = st;
        const uint32_t* AL = st + 128 * TLD16;
        const uint32_t* BH = st + 2 * 128 * TLD16;
        const uint32_t* BL = st + 3 * 128 * TLD16;
#pragma unroll
        for (int kh = 0; kh < 2; kh++) {
            const int kb = kh * 8;
            uint32_t ah[2][4], al[2][4];
#pragma unroll
            for (int mt = 0; mt < 2; mt++) {
                int R = (wm * 32 + mt * 16 + g) * TLD16 + kb + t4;
                ah[mt][0] = AH[R];              ah[mt][1] = AH[R + 8 * TLD16];
                ah[mt][2] = AH[R + 4];          ah[mt][3] = AH[R + 8 * TLD16 + 4];
                al[mt][0] = AL[R];              al[mt][1] = AL[R + 8 * TLD16];
                al[mt][2] = AL[R + 4];          al[mt][3] = AL[R + 8 * TLD16 + 4];
            }
            uint32_t bh[8][2], bl[8][2];
#pragma unroll
            for (int nt = 0; nt < 8; nt++) {
                int Cb = (wn * 64 + nt * 8 + g) * TLD16 + kb + t4;
                bh[nt][0] = BH[Cb]; bh[nt][1] = BH[Cb + 4];
                bl[nt][0] = BL[Cb]; bl[nt][1] = BL[Cb + 4];
            }
#pragma unroll
            for (int mt = 0; mt < 2; mt++)
#pragma unroll
                for (int nt = 0; nt < 8; nt++) MMA_BF16(acc[mt][nt], ah[mt], bh[nt]);
#pragma unroll
            for (int mt = 0; mt < 2; mt++)
#pragma unroll
                for (int nt = 0; nt < 8; nt++) MMA_BF16(acc[mt][nt], al[mt], bh[nt]);
#pragma unroll
            for (int mt = 0; mt < 2; mt++)
#pragma unroll
                for (int nt = 0; nt < 8; nt++) MMA_BF16(acc[mt][nt], ah[mt], bl[nt]);
        }
    }
}

// ======================= pipelined 3-term GEMM =======================
// D[M,N] = A[M,K] @ B[NB,K]^T.  MODE: 0 plain, 1 bias+relu, 2 dyn-M + row remap.
// DT: 0 = 3xTF32 (fp32-accurate), 1 = 3-term split-bf16.
template <int MODE, int DT>
__global__ __launch_bounds__(256, 1) void tc_gemm(
    const float* __restrict__ A, const float* __restrict__ Bm, float* __restrict__ Cm,
    const float* __restrict__ bias, int M, int N, int NB, int K, int lda, int ldb, int ldc)
{
    extern __shared__ uint32_t sm[];
    const int STAGE = (DT == 0) ? 4 * 128 * TLD32 : 4 * 128 * TLD16;

    const int tid = threadIdx.x;
    const int wid = tid >> 5, lane = tid & 31;
    const int g = lane >> 2, t4 = lane & 3;
    const int wm = wid & 3, wn = wid >> 2;
    const int row0 = blockIdx.y * 128, col0 = blockIdx.x * 128;
    const int Meff = (MODE == 2) ? g_hdr[1] : M;
    if (row0 >= Meff) return;

    float acc[2][8][4];
#pragma unroll
    for (int mt = 0; mt < 2; mt++)
#pragma unroll
        for (int nt = 0; nt < 8; nt++)
#pragma unroll
            for (int c = 0; c < 4; c++) acc[mt][nt][c] = 0.f;

    const int KTILES = (K + 31) >> 5;
    float4 pa[4], pb[4];

    ldg_tile(A, row0, Meff, lda, K, 0, pa, tid);
    ldg_tile(Bm, col0, NB, ldb, K, 0, pb, tid);
    sts_tile<DT>(sm, pa, pb, tid);
    __syncthreads();

    for (int kt = 0; kt < KTILES; kt++) {
        const bool has_next = (kt + 1 < KTILES);
        if (has_next) {
            int kb = (kt + 1) << 5;
            ldg_tile(A, row0, Meff, lda, K, kb, pa, tid);
            ldg_tile(Bm, col0, NB, ldb, K, kb, pb, tid);
        }
        compute_tile<DT>(sm + (kt & 1) * STAGE, acc, wm, wn, g, t4);
        if (has_next) {
            sts_tile<DT>(sm + ((kt + 1) & 1) * STAGE, pa, pb, tid);
            __syncthreads();
        }
    }

    // epilogue
#pragma unroll
    for (int mt = 0; mt < 2; mt++) {
        int rA = row0 + wm * 32 + mt * 16 + g;
        int rB = rA + 8;
        bool vA = rA < Meff, vB = rB < Meff;
        int oA = 0, oB = 0;
        if (MODE == 2) {
            if (vA) oA = g_outRow[rA];
            if (vB) oB = g_outRow[rB];
        } else { oA = rA; oB = rB; }
#pragma unroll
        for (int nt = 0; nt < 8; nt++) {
            int c0 = col0 + wn * 64 + nt * 8 + 2 * t4;
            int c1 = c0 + 1;
            float v0 = acc[mt][nt][0], v1 = acc[mt][nt][1];
            float v2 = acc[mt][nt][2], v3 = acc[mt][nt][3];
            if (MODE == 1) {
                float bb0 = (c0 < N) ? bias[c0] : 0.f;
                float bb1 = (c1 < N) ? bias[c1] : 0.f;
                v0 = fmaxf(v0 + bb0, 0.f); v1 = fmaxf(v1 + bb1, 0.f);
                v2 = fmaxf(v2 + bb0, 0.f); v3 = fmaxf(v3 + bb1, 0.f);
            }
            if (vA) {
                if (c0 < N) Cm[(size_t)oA * ldc + c0] = v0;
                if (c1 < N) Cm[(size_t)oA * ldc + c1] = v1;
            }
            if (vB) {
                if (c0 < N) Cm[(size_t)oB * ldc + c0] = v2;
                if (c1 < N) Cm[(size_t)oB * ldc + c1] = v3;
            }
        }
    }
}

// ======================= second MLP layer + log-softmax + argmax =======================
__global__ __launch_bounds__(256) void mlp2_kernel(
    const float* __restrict__ h1, const float* __restrict__ w2,
    const float* __restrict__ b2, float* __restrict__ out_logits)
{
    __shared__ float w2s[HDIM * 3];
    for (int i = threadIdx.x; i < HDIM * 3; i += 256) w2s[i] = w2[i];
    __syncthreads();
    int warp = threadIdx.x >> 5, lid = threadIdx.x & 31;
    int row = blockIdx.x * 8 + warp;
    const float* hr = h1 + (size_t)row * HDIM;
    float a0 = 0.f, a1 = 0.f, a2 = 0.f;
    for (int k = lid; k < HDIM; k += 32) {
        float h = hr[k];
        a0 += h * w2s[k * 3 + 0];
        a1 += h * w2s[k * 3 + 1];
        a2 += h * w2s[k * 3 + 2];
    }
#pragma unroll
    for (int s = 16; s > 0; s >>= 1) {
        a0 += __shfl_down_sync(0xffffffffu, a0, s);
        a1 += __shfl_down_sync(0xffffffffu, a1, s);
        a2 += __shfl_down_sync(0xffffffffu, a2, s);
    }
    if (lid == 0) {
        float l0 = a0 + b2[0], l1 = a1 + b2[1], l2 = a2 + b2[2];
        float m = fmaxf(l0, fmaxf(l1, l2));
        float lse = m + logf(expf(l0 - m) + expf(l1 - m) + expf(l2 - m));
        out_logits[(size_t)row * 3 + 0] = l0 - lse;
        out_logits[(size_t)row * 3 + 1] = l1 - lse;
        out_logits[(size_t)row * 3 + 2] = l2 - lse;
        int a = 0;
        if (l1 > l0) a = 1;
        float la = (a == 1) ? l1 : l0;
        if (l2 > la) a = 2;
        g_pred[row] = a;
    }
}

// ======================= transpose =======================
__global__ void transpose_kernel(const float* __restrict__ P, float* __restrict__ Pt,
                                 int rows, int cols)
{
    __shared__ float s[32][33];
    int c0 = blockIdx.x * 32, r0 = blockIdx.y * 32;
    int tx = threadIdx.x, ty = threadIdx.y;
#pragma unroll
    for (int t = 0; t < 4; t++) {
        int r = r0 + ty + t * 8, c = c0 + tx;
        s[ty + t * 8][tx] = (r < rows && c < cols) ? P[(size_t)r * cols + c] : 0.f;
    }
    __syncthreads();
#pragma unroll
    for (int t = 0; t < 4; t++) {
        int r = c0 + ty + t * 8, c = r0 + tx;
        if (r < cols && c < rows) Pt[(size_t)r * rows + c] = s[tx][ty + t * 8];
    }
}

// ======================= scan kernel (1 block) =======================
__global__ void scan_kernel(const int* __restrict__ labels_in, int setIdx, int usePred)
{
    __shared__ int sNZ[1024], sB[1024];
    __shared__ int s_idx0;
    __shared__ int sC[B_ROWS], sSt[B_ROWS];
    const int* lab = usePred ? (const int*)g_pred : labels_in;
    const int tid = threadIdx.x;
    const int IPT = N_TOK / 1024;
    const int base = tid * IPT;

    int cn = 0, cb = 0;
    for (int t = 0; t < IPT; t++) {
        int l = lab[base + t];
        cn += (l != 0);
        cb += (l == 1);
    }
    sNZ[tid] = cn; sB[tid] = cb;
    if (tid == 0) s_idx0 = N_TOK;
    __syncthreads();
    if (tid == 0) {
        int an = 0, ab = 0;
        for (int t = 0; t < 1024; t++) {
            int n = sNZ[t], b = sB[t];
            sNZ[t] = an; sB[t] = ab;
            an += n; ab += b;
        }
        g_hdr[0] = an;
        g_hdr[1] = ab;
    }
    __syncthreads();
    const int M = g_hdr[0], C = g_hdr[1];
    int pn = sNZ[tid], pb = sB[tid];
    for (int t = 0; t < IPT; t++) {
        int i = base + t;
        int l = lab[i];
        if (l != 0) {
            if (l == 1) { pb++; atomicMin(&s_idx0, pn); }
            g_nzTok[pn] = i;
            g_cumB[pn] = pb;
            pn++;
        }
    }
    __syncthreads();
    const int idx0 = (C > 0) ? s_idx0 : 0;
    if (tid == 0) g_hdr[2] = idx0;
    if (C > 0) {
        for (int p = tid; p < M; p += 1024) {
            int q = min(p + idx0, N_TOK - 1);
            int s = ((q < M) ? g_cumB[q] : C) - 1;
            if (p == 0) {
                g_segStart[0] = 0;
            } else {
                int q2 = min(p - 1 + idx0, N_TOK - 1);
                int s2 = ((q2 < M) ? g_cumB[q2] : C) - 1;
                if (s != s2) g_segStart[s] = p;
            }
        }
    }
    if (tid < B_ROWS) {
        int cnt = 0;
        for (int l = 0; l < L_SEQ; l++) cnt += (lab[tid * L_SEQ + l] == 1);
        sC[tid] = cnt;
    }
    __syncthreads();
    if (tid == 0) {
        int a = 0;
        for (int b = 0; b < B_ROWS; b++) { sSt[b] = a; a += sC[b]; }
    }
    __syncthreads();
    if (tid < B_ROWS) {
        g_c[setIdx][tid] = sC[tid];
        int st = sSt[tid];
        for (int j = 0; j < sC[tid]; j++) g_outRow[st + j] = tid * L_SEQ + j;
    }
}

// ======================= segment means =======================
__global__ void means_kernel(const float* __restrict__ hidden)
{
    const int C = g_hdr[1], M = g_hdr[0];
    const int tid = threadIdx.x;
    for (int s = blockIdx.x; s < C; s += gridDim.x) {
        int st = g_segStart[s];
        int en = (s + 1 < C) ? g_segStart[s + 1] : M;
        float a0 = 0.f, a1 = 0.f, a2 = 0.f;
        for (int p = st; p < en; p++) {
            const float* h = hidden + (size_t)g_nzTok[p] * HDIM;
            a0 += h[tid];
            a1 += h[tid + 256];
            a2 += h[tid + 512];
        }
        float inv = 1.f / (float)(en - st);
        float* m = g_means + (size_t)s * HDIM;
        m[tid] = a0 * inv;
        m[tid + 256] = a1 * inv;
        m[tid + 512] = a2 * inv;
    }
}

// ======================= row-wise log-softmax over E =======================
__global__ void softmax_kernel(float* __restrict__ scores)
{
    __shared__ float red[256];
    const int gid = blockIdx.x;
    const int set = gid >> 15;
    const int r = gid & (N_TOK - 1);
    const int b = r / L_SEQ, j = r - b * L_SEQ;
    float* row = scores + (size_t)set * N_TOK * EDIM + (size_t)r * EDIM;
    const int tid = threadIdx.x;
    const int NV = EDIM / 4;

    if (j >= g_c[set][b]) {
        const float c = -6.9077552789821368f;
        if (tid < NV) reinterpret_cast<float4*>(row)[tid] = make_float4(c, c, c, c);
        return;
    }
    float4 v = make_float4(0.f, 0.f, 0.f, 0.f);
    float m = -3.0e38f;
    if (tid < NV) {
        v = reinterpret_cast<const float4*>(row)[tid];
        m = fmaxf(fmaxf(v.x, v.y), fmaxf(v.z, v.w));
    }
    red[tid] = m;
    __syncthreads();
    for (int s = 128; s > 0; s >>= 1) {
        if (tid < s) red[tid] = fmaxf(red[tid], red[tid + s]);
        __syncthreads();
    }
    float vmax = red[0];
    __syncthreads();
    float se = 0.f;
    if (tid < NV)
        se = expf(v.x - vmax) + expf(v.y - vmax) + expf(v.z - vmax) + expf(v.w - vmax);
    red[tid] = se;
    __syncthreads();
    for (int s = 128; s > 0; s >>= 1) {
        if (tid < s) red[tid] += red[tid + s];
        __syncthreads();
    }
    float lse = vmax + logf(red[0]);
    if (tid < NV) {
        v.x -= lse; v.y -= lse; v.z -= lse; v.w -= lse;
        reinterpret_cast<float4*>(row)[tid] = v;
    }
}

// ======================= launch =======================
#define SMEM_TF32 (2 * 4 * 128 * TLD32 * 4)   // 147456 B
#define SMEM_BF16 (2 * 4 * 128 * TLD16 * 4)   // 81920 B

extern "C" void kernel_launch(void* const* d_in, const int* in_sizes, int n_in,
                              void* d_out, int out_size)
{
    const int*   labels    = (const int*)d_in[0];
    const float* hidden    = (const float*)d_in[1];
    const float* ent       = (const float*)d_in[2];
    const float* w1        = (const float*)d_in[3];
    const float* b1        = (const float*)d_in[4];
    const float* w2        = (const float*)d_in[5];
    const float* b2        = (const float*)d_in[6];
    const float* w_mention = (const float*)d_in[7];
    const float* w_desc    = (const float*)d_in[8];
    float* out = (float*)d_out;

    cudaFuncSetAttribute(tc_gemm<1, 0>, cudaFuncAttributeMaxDynamicSharedMemorySize, SMEM_TF32);
    cudaFuncSetAttribute(tc_gemm<0, 1>, cudaFuncAttributeMaxDynamicSharedMemorySize, SMEM_BF16);
    cudaFuncSetAttribute(tc_gemm<2, 1>, cudaFuncAttributeMaxDynamicSharedMemorySize, SMEM_BF16);

    void *pP, *pQt, *pMeans, *pH1, *pW1t, *pWdT;
    cudaGetSymbolAddress(&pP, g_P);
    cudaGetSymbolAddress(&pQt, g_Qt);
    cudaGetSymbolAddress(&pMeans, g_means);
    cudaGetSymbolAddress(&pH1, g_h1);
    cudaGetSymbolAddress(&pW1t, g_w1t);
    cudaGetSymbolAddress(&pWdT, g_wdT);

    // transposes: w1t = w1^T [768x768], wdT = w_desc^T [300x768]
    transpose_kernel<<<dim3(24, 24), dim3(32, 8)>>>(w1, (float*)pW1t, HDIM, HDIM);
    transpose_kernel<<<dim3(10, 24), dim3(32, 8)>>>(w_desc, (float*)pWdT, HDIM, PDIM);

    // h1 = relu(hidden @ w1 + b1)  -- fp32-accurate 3xTF32 (argmax must not flip)
    tc_gemm<1, 0><<<dim3(6, 256), 256, SMEM_TF32>>>(
        hidden, (const float*)pW1t, (float*)pH1, b1,
        N_TOK, HDIM, HDIM, HDIM, HDIM, HDIM, HDIM);

    // logits + argmax
    mlp2_kernel<<<N_TOK / 8, 256>>>((const float*)pH1, w2, b2, out);

    // P = ent @ w_desc   [1000 x 300]  (bf16 3-term)
    tc_gemm<0, 1><<<dim3(3, 8), 256, SMEM_BF16>>>(
        ent, (const float*)pWdT, (float*)pP, nullptr,
        EDIM, PDIM, PDIM, HDIM, HDIM, HDIM, PDIM);

    // Qt = P @ w_mention^T   [1000 x 768]  (bf16 3-term)
    tc_gemm<0, 1><<<dim3(6, 8), 256, SMEM_BF16>>>(
        (const float*)pP, w_mention, (float*)pQt, nullptr,
        EDIM, HDIM, HDIM, PDIM, PDIM, PDIM, HDIM);

    float* score_base = out + (size_t)N_TOK * 3;

    for (int set = 0; set < 2; set++) {
        scan_kernel<<<1, 1024>>>(labels, set, set);
        means_kernel<<<4096, 256>>>(hidden);
        // scores = means @ Qt^T  (bf16 3-term) -> remapped rows of out
        tc_gemm<2, 1><<<dim3(8, 256), 256, SMEM_BF16>>>(
            (const float*)pMeans, (const float*)pQt,
            score_base + (size_t)set * N_TOK * EDIM, nullptr,
            N_TOK, EDIM, 1024, HDIM, HDIM, HDIM, EDIM);
    }

    softmax_kernel<<<2 * N_TOK, 256>>>(score_base);
}